// round 16
// baseline (speedup 1.0000x reference)
#include <cuda_runtime.h>
#include <cuda_fp16.h>
#include <mma.h>
using namespace nvcuda;

#define Nn   10000
#define Ne   320000
#define EAt  330000      // edges + self loops
#define HID  256
#define NRED 157         // one partial per gemm_pol block

// ---------------- scratch (static device globals; zero-initialized at load) ------
__device__ float2   g_cl[Nn];          // (incoming count, edge_attr sum)
__device__ int      g_row[Nn+1];
__device__ int      g_woff[Nn];
__device__ int4     g_ced[EAt];        // (src, ea_bits, x01_half2, x23_half2)
__device__ __half2  g_xlh[Nn*128];     // fp16 xl feature table (edge-gathered)
__device__ __half2  g_hh[Nn*128];      // fp16 activations: conv1 out, then conv2 out
__device__ float    g_xr[Nn*HID];
__device__ float    g_pl[Nn*4];
__device__ float    g_pmax[NRED];
__device__ float    g_psum[NRED];

__device__ __forceinline__ void red2(float2* p, float a, float b){
    asm volatile("red.global.add.v2.f32 [%0], {%1,%2};" :: "l"(p), "f"(a), "f"(b) : "memory");
}

// half2 logit kernel: p_lane = Σ_j [ (0.6att)·z + (0.4att)·|z| ],  z = la + r + ev·w
__device__ __forceinline__ float dot8h(const __half2* la, const __half2* rh,
                                       const __half2* wh, const __half2* a06,
                                       const __half2* a04, __half2 evh){
    __half2 pa = __float2half2_rn(0.f), pb = __float2half2_rn(0.f);
    #pragma unroll
    for(int j4 = 0; j4 < 4; j4++){
        __half2 z = __hfma2(evh, wh[j4], __hadd2(la[j4], rh[j4]));
        pa = __hfma2(z, a06[j4], pa);
        pb = __hfma2(__habs2(z), a04[j4], pb);
    }
    float2 f = __half22float2(__hadd2(pa, pb));
    return f.x + f.y;
}

// extract this lane's x value (j = lane&3) from the packed edge record
__device__ __forceinline__ float xsel(int4 ed, int j){
    unsigned bits = (j & 2) ? (unsigned)ed.w : (unsigned)ed.z;
    float2 f = __half22float2(*(__half2*)&bits);
    return (j & 1) ? f.y : f.x;
}

// ---------------- kernel 1: edge histogram (vector red)  ||  lin1 ----------------
#define HB 1250   // (Ne+255)/256
__global__ void k_hist_lin1(const int* __restrict__ dst, const float* __restrict__ ea,
                            const float* __restrict__ x,
                            const float* __restrict__ Wl, const float* __restrict__ bl,
                            const float* __restrict__ Wr, const float* __restrict__ br){
    int b = blockIdx.x;
    if(b < HB){
        int e = b*256 + threadIdx.x;
        if(e < Ne)
            red2(&g_cl[dst[e]], 1.f, ea[e]);
    } else {
        int t = (b - HB)*256 + threadIdx.x;
        if(t < Nn*64){
            int n = t >> 6, c4 = (t & 63) << 2;
            float4 xv = *(const float4*)(x + n*4);
            float4 l = *(const float4*)(bl + c4);
            float4 r = *(const float4*)(br + c4);
            float4 w;
            w = *(const float4*)(Wl + 0*256 + c4); l.x+=xv.x*w.x; l.y+=xv.x*w.y; l.z+=xv.x*w.z; l.w+=xv.x*w.w;
            w = *(const float4*)(Wl + 1*256 + c4); l.x+=xv.y*w.x; l.y+=xv.y*w.y; l.z+=xv.y*w.z; l.w+=xv.y*w.w;
            w = *(const float4*)(Wl + 2*256 + c4); l.x+=xv.z*w.x; l.y+=xv.z*w.y; l.z+=xv.z*w.z; l.w+=xv.z*w.w;
            w = *(const float4*)(Wl + 3*256 + c4); l.x+=xv.w*w.x; l.y+=xv.w*w.y; l.z+=xv.w*w.z; l.w+=xv.w*w.w;
            w = *(const float4*)(Wr + 0*256 + c4); r.x+=xv.x*w.x; r.y+=xv.x*w.y; r.z+=xv.x*w.z; r.w+=xv.x*w.w;
            w = *(const float4*)(Wr + 1*256 + c4); r.x+=xv.y*w.x; r.y+=xv.y*w.y; r.z+=xv.y*w.z; r.w+=xv.y*w.w;
            w = *(const float4*)(Wr + 2*256 + c4); r.x+=xv.z*w.x; r.y+=xv.z*w.y; r.z+=xv.z*w.z; r.w+=xv.z*w.w;
            w = *(const float4*)(Wr + 3*256 + c4); r.x+=xv.w*w.x; r.y+=xv.w*w.y; r.z+=xv.w*w.z; r.w+=xv.w*w.w;
            __half2 h0 = __floats2half2_rn(l.x, l.y);
            __half2 h1 = __floats2half2_rn(l.z, l.w);
            __half2* dst2 = g_xlh + n*128 + (c4 >> 1);
            dst2[0] = h0; dst2[1] = h1;
            *(float4*)(g_xr + n*256 + c4) = r;
        }
    }
}

// ---------------- kernel 2: scan + prep (single block) ----------------
__global__ void k_scanprep(const float* __restrict__ x){
    __shared__ int part[1024];
    const int NP = 10;
    int tid = threadIdx.x;
    int base = tid * NP;
    int cnt[NP], loc[NP];
    int s = 0;
    #pragma unroll
    for(int i = 0; i < NP; i++){
        int idx = base + i;
        int c = (idx < Nn) ? (int)g_cl[idx].x : 0;
        cnt[i] = c;
        loc[i] = s;
        s += (idx < Nn) ? (c + 1) : 0;
    }
    part[tid] = s; __syncthreads();
    for(int o = 1; o < 1024; o <<= 1){
        int v = (tid >= o) ? part[tid - o] : 0;
        __syncthreads();
        if(tid >= o) part[tid] += v;
        __syncthreads();
    }
    int off = (tid > 0) ? part[tid - 1] : 0;
    #pragma unroll
    for(int i = 0; i < NP; i++){
        int idx = base + i;
        if(idx < Nn){
            int rs = off + loc[i];
            int re = rs + cnt[i] + 1;
            g_row[idx] = rs;
            if(idx == Nn-1) g_row[Nn] = re;
            float lp = g_cl[idx].y / fmaxf((float)cnt[i], 1.f);
            float4 xv = *(const float4*)(x + idx*4);
            __half2 x01 = __floats2half2_rn(xv.x, xv.y);
            __half2 x23 = __floats2half2_rn(xv.z, xv.w);
            g_ced[re-1] = make_int4(idx, __float_as_int(lp),
                                    *(int*)&x01, *(int*)&x23);
            g_woff[idx] = rs;
        }
    }
}

// ---------------- kernel 3: scatter edges into CSR (with packed x) ----------------
__global__ void k_scatter(const int* __restrict__ src, const int* __restrict__ dst,
                          const float* __restrict__ ea, const float* __restrict__ x){
    int e = blockIdx.x*blockDim.x + threadIdx.x;
    if(e >= Ne) return;
    int d = dst[e];
    int s = src[e];
    float4 xv = *(const float4*)(x + s*4);
    int pos = atomicAdd(&g_woff[d], 1);
    __half2 x01 = __floats2half2_rn(xv.x, xv.y);
    __half2 x23 = __floats2half2_rn(xv.z, xv.w);
    g_ced[pos] = make_int4(s, __float_as_int(ea[e]), *(int*)&x01, *(int*)&x23);
}

// ---------------- fused conv1 (low-rank aggregation; half2 logit path) -----------
__global__ void __launch_bounds__(32) k_conv1lr(
        const float* __restrict__ Wl, const float* __restrict__ bl,
        const float* __restrict__ We, const float* __restrict__ att,
        const float* __restrict__ bias, const float* __restrict__ gam,
        const float* __restrict__ bet){
    int n = blockIdx.x;
    int lane = threadIdx.x;
    int c0 = lane * 8;
    __half2 rh[4], wh[4], a06[4], a04[4];
    {
        float4 rA = *(const float4*)(g_xr + n*HID + c0);
        float4 rB = *(const float4*)(g_xr + n*HID + c0 + 4);
        rh[0] = __floats2half2_rn(rA.x, rA.y); rh[1] = __floats2half2_rn(rA.z, rA.w);
        rh[2] = __floats2half2_rn(rB.x, rB.y); rh[3] = __floats2half2_rn(rB.z, rB.w);
        float4 wA = *(const float4*)(We + c0), wB = *(const float4*)(We + c0 + 4);
        wh[0] = __floats2half2_rn(wA.x, wA.y); wh[1] = __floats2half2_rn(wA.z, wA.w);
        wh[2] = __floats2half2_rn(wB.x, wB.y); wh[3] = __floats2half2_rn(wB.z, wB.w);
        float4 tA = *(const float4*)(att + c0), tB = *(const float4*)(att + c0 + 4);
        a06[0] = __floats2half2_rn(0.6f*tA.x, 0.6f*tA.y); a06[1] = __floats2half2_rn(0.6f*tA.z, 0.6f*tA.w);
        a06[2] = __floats2half2_rn(0.6f*tB.x, 0.6f*tB.y); a06[3] = __floats2half2_rn(0.6f*tB.z, 0.6f*tB.w);
        a04[0] = __floats2half2_rn(0.4f*tA.x, 0.4f*tA.y); a04[1] = __floats2half2_rn(0.4f*tA.z, 0.4f*tA.w);
        a04[2] = __floats2half2_rn(0.4f*tB.x, 0.4f*tB.y); a04[3] = __floats2half2_rn(0.4f*tB.z, 0.4f*tB.w);
    }
    int j = lane & 3;
    float acc1 = 0.f, den = 0.f;
    int b = g_row[n], e = g_row[n+1];
    int i = b;
    for(; i + 1 < e; i += 2){
        int4 ed0 = g_ced[i], ed1 = g_ced[i+1];
        uint4 raw0 = *(const uint4*)(g_xlh + ed0.x*128 + lane*4);
        uint4 raw1 = *(const uint4*)(g_xlh + ed1.x*128 + lane*4);
        const __half2* la = (const __half2*)&raw0;
        const __half2* lb = (const __half2*)&raw1;
        __half2 evh0 = __float2half2_rn(__int_as_float(ed0.y));
        __half2 evh1 = __float2half2_rn(__int_as_float(ed1.y));
        float xs0 = xsel(ed0, j);
        float xs1 = xsel(ed1, j);
        float p0 = dot8h(la, rh, wh, a06, a04, evh0);
        float p1 = dot8h(lb, rh, wh, a06, a04, evh1);
        #pragma unroll
        for(int o = 0; o < 3; o++){
            p0 += __shfl_xor_sync(0xffffffffu, p0, 1 << o);
            p1 += __shfl_xor_sync(0xffffffffu, p1, 1 << o);
        }
        float e0 = __expf(p0);
        float e1 = __expf(p1);
        den += e0 + e1;
        acc1 += xs0*e0 + xs1*e1;
    }
    if(i < e){
        int4 ed0 = g_ced[i];
        uint4 raw0 = *(const uint4*)(g_xlh + ed0.x*128 + lane*4);
        const __half2* la = (const __half2*)&raw0;
        __half2 evh0 = __float2half2_rn(__int_as_float(ed0.y));
        float xs0 = xsel(ed0, j);
        float p0 = dot8h(la, rh, wh, a06, a04, evh0);
        #pragma unroll
        for(int o = 0; o < 3; o++)
            p0 += __shfl_xor_sync(0xffffffffu, p0, 1 << o);
        float e0 = __expf(p0);
        den += e0;
        acc1 += xs0*e0;
    }
    float inv = 1.f / den;
    int h8 = lane & 24;
    float ax0 = __shfl_sync(0xffffffffu, acc1, h8+0) * inv;
    float ax1 = __shfl_sync(0xffffffffu, acc1, h8+1) * inv;
    float ax2 = __shfl_sync(0xffffffffu, acc1, h8+2) * inv;
    float ax3 = __shfl_sync(0xffffffffu, acc1, h8+3) * inv;
    float4 wr0A = *(const float4*)(Wl + 0*256 + c0), wr0B = *(const float4*)(Wl + 0*256 + c0 + 4);
    float4 wr1A = *(const float4*)(Wl + 1*256 + c0), wr1B = *(const float4*)(Wl + 1*256 + c0 + 4);
    float4 wr2A = *(const float4*)(Wl + 2*256 + c0), wr2B = *(const float4*)(Wl + 2*256 + c0 + 4);
    float4 wr3A = *(const float4*)(Wl + 3*256 + c0), wr3B = *(const float4*)(Wl + 3*256 + c0 + 4);
    float4 blA = *(const float4*)(bl + c0),   blB = *(const float4*)(bl + c0 + 4);
    float4 biA = *(const float4*)(bias + c0), biB = *(const float4*)(bias + c0 + 4);
    float v[8];
    v[0] = ax0*wr0A.x + ax1*wr1A.x + ax2*wr2A.x + ax3*wr3A.x + blA.x + biA.x;
    v[1] = ax0*wr0A.y + ax1*wr1A.y + ax2*wr2A.y + ax3*wr3A.y + blA.y + biA.y;
    v[2] = ax0*wr0A.z + ax1*wr1A.z + ax2*wr2A.z + ax3*wr3A.z + blA.z + biA.z;
    v[3] = ax0*wr0A.w + ax1*wr1A.w + ax2*wr2A.w + ax3*wr3A.w + blA.w + biA.w;
    v[4] = ax0*wr0B.x + ax1*wr1B.x + ax2*wr2B.x + ax3*wr3B.x + blB.x + biB.x;
    v[5] = ax0*wr0B.y + ax1*wr1B.y + ax2*wr2B.y + ax3*wr3B.y + blB.y + biB.y;
    v[6] = ax0*wr0B.z + ax1*wr1B.z + ax2*wr2B.z + ax3*wr3B.z + blB.z + biB.z;
    v[7] = ax0*wr0B.w + ax1*wr1B.w + ax2*wr2B.w + ax3*wr3B.w + blB.w + biB.w;
    float s = 0.f;
    #pragma unroll
    for(int k = 0; k < 8; k++) s += v[k];
    #pragma unroll
    for(int o = 16; o; o >>= 1) s += __shfl_xor_sync(0xffffffffu, s, o);
    float mu = s * (1.f/256.f);
    float q = 0.f;
    #pragma unroll
    for(int k = 0; k < 8; k++){ float dd = v[k]-mu; q += dd*dd; }
    #pragma unroll
    for(int o = 16; o; o >>= 1) q += __shfl_xor_sync(0xffffffffu, q, o);
    float rstd = rsqrtf(q*(1.f/256.f) + 1e-5f);
    float4 gA = *(const float4*)(gam + c0), gB = *(const float4*)(gam + c0 + 4);
    float4 eA = *(const float4*)(bet + c0), eB = *(const float4*)(bet + c0 + 4);
    float gv[8] = {gA.x,gA.y,gA.z,gA.w,gB.x,gB.y,gB.z,gB.w};
    float ev[8] = {eA.x,eA.y,eA.z,eA.w,eB.x,eB.y,eB.z,eB.w};
    float o0[8];
    #pragma unroll
    for(int k = 0; k < 8; k++)
        o0[k] = fmaxf((v[k]-mu)*rstd*gv[k] + ev[k], 0.f);
    __half2* dh = g_hh + n*128 + lane*4;
    dh[0] = __floats2half2_rn(o0[0], o0[1]);
    dh[1] = __floats2half2_rn(o0[2], o0[3]);
    dh[2] = __floats2half2_rn(o0[4], o0[5]);
    dh[3] = __floats2half2_rn(o0[6], o0[7]);
}

// ---------------- fused conv2: half2 logits + half2 aggregation w/ fp32 flush ----
__global__ void __launch_bounds__(32) k_conv2(
        const float* __restrict__ We, const float* __restrict__ att,
        const float* __restrict__ bias, const float* __restrict__ gam,
        const float* __restrict__ bet){
    int n = blockIdx.x;
    int lane = threadIdx.x;
    int c0 = lane * 8;
    __half2 rh[4], wh[4], a06[4], a04[4];
    {
        float4 rA = *(const float4*)(g_xr + n*HID + c0);
        float4 rB = *(const float4*)(g_xr + n*HID + c0 + 4);
        rh[0] = __floats2half2_rn(rA.x, rA.y); rh[1] = __floats2half2_rn(rA.z, rA.w);
        rh[2] = __floats2half2_rn(rB.x, rB.y); rh[3] = __floats2half2_rn(rB.z, rB.w);
        float4 wA = *(const float4*)(We + c0), wB = *(const float4*)(We + c0 + 4);
        wh[0] = __floats2half2_rn(wA.x, wA.y); wh[1] = __floats2half2_rn(wA.z, wA.w);
        wh[2] = __floats2half2_rn(wB.x, wB.y); wh[3] = __floats2half2_rn(wB.z, wB.w);
        float4 tA = *(const float4*)(att + c0), tB = *(const float4*)(att + c0 + 4);
        a06[0] = __floats2half2_rn(0.6f*tA.x, 0.6f*tA.y); a06[1] = __floats2half2_rn(0.6f*tA.z, 0.6f*tA.w);
        a06[2] = __floats2half2_rn(0.6f*tB.x, 0.6f*tB.y); a06[3] = __floats2half2_rn(0.6f*tB.z, 0.6f*tB.w);
        a04[0] = __floats2half2_rn(0.4f*tA.x, 0.4f*tA.y); a04[1] = __floats2half2_rn(0.4f*tA.z, 0.4f*tA.w);
        a04[2] = __floats2half2_rn(0.4f*tB.x, 0.4f*tB.y); a04[3] = __floats2half2_rn(0.4f*tB.z, 0.4f*tB.w);
    }
    float acc[8] = {0,0,0,0,0,0,0,0};
    __half2 zero2 = __float2half2_rn(0.f);
    __half2 hacc[4] = {zero2, zero2, zero2, zero2};
    float den = 0.f;
    int flush = 0;
    int b = g_row[n], e = g_row[n+1];
    int i = b;
    for(; i + 1 < e; i += 2){
        int4 ed0 = g_ced[i], ed1 = g_ced[i+1];
        uint4 raw0 = *(const uint4*)(g_xlh + ed0.x*128 + lane*4);
        uint4 raw1 = *(const uint4*)(g_xlh + ed1.x*128 + lane*4);
        const __half2* la = (const __half2*)&raw0;
        const __half2* lb = (const __half2*)&raw1;
        __half2 evh0 = __float2half2_rn(__int_as_float(ed0.y));
        __half2 evh1 = __float2half2_rn(__int_as_float(ed1.y));
        float p0 = dot8h(la, rh, wh, a06, a04, evh0);
        float p1 = dot8h(lb, rh, wh, a06, a04, evh1);
        #pragma unroll
        for(int o = 0; o < 5; o++){
            p0 += __shfl_xor_sync(0xffffffffu, p0, 1 << o);
            p1 += __shfl_xor_sync(0xffffffffu, p1, 1 << o);
        }
        float e0 = __expf(p0);
        float e1 = __expf(p1);
        den += e0 + e1;
        __half2 eh0 = __float2half2_rn(e0);
        __half2 eh1 = __float2half2_rn(e1);
        #pragma unroll
        for(int j4 = 0; j4 < 4; j4++){
            hacc[j4] = __hfma2(la[j4], eh0, hacc[j4]);
            hacc[j4] = __hfma2(lb[j4], eh1, hacc[j4]);
        }
        if(++flush == 4){
            flush = 0;
            #pragma unroll
            for(int j4 = 0; j4 < 4; j4++){
                float2 f = __half22float2(hacc[j4]);
                acc[2*j4]   += f.x;
                acc[2*j4+1] += f.y;
                hacc[j4] = zero2;
            }
        }
    }
    if(i < e){
        int4 ed0 = g_ced[i];
        uint4 raw0 = *(const uint4*)(g_xlh + ed0.x*128 + lane*4);
        const __half2* la = (const __half2*)&raw0;
        __half2 evh0 = __float2half2_rn(__int_as_float(ed0.y));
        float p0 = dot8h(la, rh, wh, a06, a04, evh0);
        #pragma unroll
        for(int o = 0; o < 5; o++)
            p0 += __shfl_xor_sync(0xffffffffu, p0, 1 << o);
        float e0 = __expf(p0);
        den += e0;
        __half2 eh0 = __float2half2_rn(e0);
        #pragma unroll
        for(int j4 = 0; j4 < 4; j4++)
            hacc[j4] = __hfma2(la[j4], eh0, hacc[j4]);
    }
    #pragma unroll
    for(int j4 = 0; j4 < 4; j4++){
        float2 f = __half22float2(hacc[j4]);
        acc[2*j4]   += f.x;
        acc[2*j4+1] += f.y;
    }
    float inv = 1.f / den;
    float4 biA = *(const float4*)(bias + c0), biB = *(const float4*)(bias + c0 + 4);
    float bi[8] = {biA.x,biA.y,biA.z,biA.w,biB.x,biB.y,biB.z,biB.w};
    float v[8];
    float s = 0.f;
    #pragma unroll
    for(int k = 0; k < 8; k++){ v[k] = acc[k]*inv + bi[k]; s += v[k]; }
    #pragma unroll
    for(int o = 16; o; o >>= 1) s += __shfl_xor_sync(0xffffffffu, s, o);
    float mu = s * (1.f/256.f);
    float q = 0.f;
    #pragma unroll
    for(int k = 0; k < 8; k++){ float dd = v[k]-mu; q += dd*dd; }
    #pragma unroll
    for(int o = 16; o; o >>= 1) q += __shfl_xor_sync(0xffffffffu, q, o);
    float rstd = rsqrtf(q*(1.f/256.f) + 1e-5f);
    float4 gA = *(const float4*)(gam + c0), gB = *(const float4*)(gam + c0 + 4);
    float4 eA = *(const float4*)(bet + c0), eB = *(const float4*)(bet + c0 + 4);
    float gv[8] = {gA.x,gA.y,gA.z,gA.w,gB.x,gB.y,gB.z,gB.w};
    float evv[8] = {eA.x,eA.y,eA.z,eA.w,eB.x,eB.y,eB.z,eB.w};
    float o0[8];
    #pragma unroll
    for(int k = 0; k < 8; k++)
        o0[k] = fmaxf((v[k]-mu)*rstd*gv[k] + evv[k], 0.f);
    __half2* dh = g_hh + n*128 + lane*4;
    dh[0] = __floats2half2_rn(o0[0], o0[1]);
    dh[1] = __floats2half2_rn(o0[2], o0[3]);
    dh[2] = __floats2half2_rn(o0[4], o0[5]);
    dh[3] = __floats2half2_rn(o0[6], o0[7]);
}

// ---------------- dual GEMM: fp16 tensor cores (m16n16k16, fp32 accum) ----------
__global__ void __launch_bounds__(128) k_gemm_dual(
        const float* __restrict__ Wl, const float* __restrict__ bl,
        const float* __restrict__ Wr, const float* __restrict__ br){
    __shared__ __align__(16) __half As[64][40];
    __shared__ __align__(16) __half Bs[32][72];
    __shared__ __align__(16) float  Cs[64][68];
    int half_ = blockIdx.x >> 2;
    int nblk = blockIdx.x & 3;
    const float* B    = half_ ? Wr : Wl;
    const float* bias = half_ ? br : bl;
    int m0 = blockIdx.y*64, n0 = nblk*64;
    int t = threadIdx.x;
    int warp = t >> 5, wy = warp >> 1, wx = warp & 1;

    wmma::fragment<wmma::accumulator,16,16,16,float> acc[2][2];
    #pragma unroll
    for(int i = 0; i < 2; i++)
        #pragma unroll
        for(int jj = 0; jj < 2; jj++)
            wmma::fill_fragment(acc[i][jj], 0.f);

    int arow = t >> 1, aseg = t & 1;
    int brow = t >> 2, bcol = (t & 3) * 16;
    for(int k0 = 0; k0 < 256; k0 += 32){
        int gm = m0 + arow;
        uint4 z4 = make_uint4(0,0,0,0);
        const uint4* srcA = (const uint4*)(g_hh + gm*128 + (k0 >> 1) + aseg*8);
        uint4 av0 = (gm < Nn) ? srcA[0] : z4;
        uint4 av1 = (gm < Nn) ? srcA[1] : z4;
        *(uint4*)&As[arow][aseg*16]     = av0;
        *(uint4*)&As[arow][aseg*16 + 8] = av1;
        const float4* srcB = (const float4*)(B + (k0+brow)*256 + n0 + bcol);
        float4 f0 = srcB[0], f1 = srcB[1], f2 = srcB[2], f3 = srcB[3];
        __half2* db = (__half2*)&Bs[brow][bcol];
        db[0] = __floats2half2_rn(f0.x,f0.y); db[1] = __floats2half2_rn(f0.z,f0.w);
        db[2] = __floats2half2_rn(f1.x,f1.y); db[3] = __floats2half2_rn(f1.z,f1.w);
        db[4] = __floats2half2_rn(f2.x,f2.y); db[5] = __floats2half2_rn(f2.z,f2.w);
        db[6] = __floats2half2_rn(f3.x,f3.y); db[7] = __floats2half2_rn(f3.z,f3.w);
        __syncthreads();
        #pragma unroll
        for(int ks = 0; ks < 2; ks++){
            wmma::fragment<wmma::matrix_a,16,16,16,__half,wmma::row_major> af[2];
            wmma::fragment<wmma::matrix_b,16,16,16,__half,wmma::row_major> bf[2];
            #pragma unroll
            for(int i = 0; i < 2; i++)
                wmma::load_matrix_sync(af[i], &As[wy*32 + i*16][ks*16], 40);
            #pragma unroll
            for(int jj = 0; jj < 2; jj++)
                wmma::load_matrix_sync(bf[jj], &Bs[ks*16][wx*32 + jj*16], 72);
            #pragma unroll
            for(int i = 0; i < 2; i++)
                #pragma unroll
                for(int jj = 0; jj < 2; jj++)
                    wmma::mma_sync(acc[i][jj], af[i], bf[jj], acc[i][jj]);
        }
        __syncthreads();
    }
    #pragma unroll
    for(int i = 0; i < 2; i++)
        #pragma unroll
        for(int jj = 0; jj < 2; jj++)
            wmma::store_matrix_sync(&Cs[wy*32 + i*16][wx*32 + jj*16], acc[i][jj], 68, wmma::mem_row_major);
    __syncthreads();
    for(int idx = t; idx < 64*16; idx += 128){
        int row = idx >> 4;
        int c4 = (idx & 15) * 4;
        int gm = m0 + row;
        if(gm >= Nn) continue;
        float4 v = *(float4*)&Cs[row][c4];
        float4 bv = *(const float4*)(bias + n0 + c4);
        v.x += bv.x; v.y += bv.y; v.z += bv.z; v.w += bv.w;
        if(half_){
            *(float4*)(g_xr + gm*256 + n0 + c4) = v;
        } else {
            __half2* d2 = g_xlh + gm*128 + ((n0 + c4) >> 1);
            d2[0] = __floats2half2_rn(v.x, v.y);
            d2[1] = __floats2half2_rn(v.z, v.w);
        }
    }
}

// ---------------- policy GEMM: fp16 TC + fused Wp2 projection + softmax partials --
__global__ void __launch_bounds__(128) k_gemm_pol(
        const float* __restrict__ Wp1, const float* __restrict__ bp1,
        const float* __restrict__ Wp2, const float* __restrict__ bp2){
    __shared__ __align__(16) __half As[64][40];
    __shared__ __align__(16) __half Bs[32][136];
    __shared__ __align__(16) float  Cs[64][132];
    int m0 = blockIdx.x * 64;
    int t = threadIdx.x;
    int warp = t >> 5, wy = warp >> 1, wx = warp & 1;

    wmma::fragment<wmma::accumulator,16,16,16,float> acc[2][4];
    #pragma unroll
    for(int i = 0; i < 2; i++)
        #pragma unroll
        for(int jj = 0; jj < 4; jj++)
            wmma::fill_fragment(acc[i][jj], 0.f);

    int arow = t >> 1, aseg = t & 1;
    int brow = t >> 2, bcol = (t & 3) * 32;
    for(int k0 = 0; k0 < 256; k0 += 32){
        int gm = m0 + arow;
        uint4 z4 = make_uint4(0,0,0,0);
        const uint4* srcA = (const uint4*)(g_hh + gm*128 + (k0 >> 1) + aseg*8);
        uint4 av0 = (gm < Nn) ? srcA[0] : z4;
        uint4 av1 = (gm < Nn) ? srcA[1] : z4;
        *(uint4*)&As[arow][aseg*16]     = av0;
        *(uint4*)&As[arow][aseg*16 + 8] = av1;
        const float4* srcB = (const float4*)(Wp1 + (k0+brow)*128 + bcol);
        __half2* db = (__half2*)&Bs[brow][bcol];
        #pragma unroll
        for(int q = 0; q < 8; q++){
            float4 f = srcB[q];
            db[2*q]   = __floats2half2_rn(f.x, f.y);
            db[2*q+1] = __floats2half2_rn(f.z, f.w);
        }
        __syncthreads();
        #pragma unroll
        for(int ks = 0; ks < 2; ks++){
            wmma::fragment<wmma::matrix_a,16,16,16,__half,wmma::row_major> af[2];
            wmma::fragment<wmma::matrix_b,16,16,16,__half,wmma::row_major> bf[4];
            #pragma unroll
            for(int i = 0; i < 2; i++)
                wmma::load_matrix_sync(af[i], &As[wy*32 + i*16][ks*16], 40);
            #pragma unroll
            for(int jj = 0; jj < 4; jj++)
                wmma::load_matrix_sync(bf[jj], &Bs[ks*16][wx*64 + jj*16], 136);
            #pragma unroll
            for(int i = 0; i < 2; i++)
                #pragma unroll
                for(int jj = 0; jj < 4; jj++)
                    wmma::mma_sync(acc[i][jj], af[i], bf[jj], acc[i][jj]);
        }
        __syncthreads();
    }
    #pragma unroll
    for(int i = 0; i < 2; i++)
        #pragma unroll
        for(int jj = 0; jj < 4; jj++)
            wmma::store_matrix_sync(&Cs[wy*32 + i*16][wx*64 + jj*16], acc[i][jj], 132, wmma::mem_row_major);
    __syncthreads();
    int row = t >> 1;
    int seg = t & 1;
    int gm = m0 + row;
    float part0 = 0.f, part1 = 0.f, part2 = 0.f, part3 = 0.f;
    #pragma unroll 8
    for(int jq = 0; jq < 64; jq++){
        int col = seg*64 + jq;
        float v = fmaxf(Cs[row][col] + bp1[col], 0.f);
        const float4 wv = *(const float4*)(Wp2 + col*4);
        part0 += v*wv.x; part1 += v*wv.y; part2 += v*wv.z; part3 += v*wv.w;
    }
    part0 += __shfl_xor_sync(0xffffffffu, part0, 1);
    part1 += __shfl_xor_sync(0xffffffffu, part1, 1);
    part2 += __shfl_xor_sync(0xffffffffu, part2, 1);
    part3 += __shfl_xor_sync(0xffffffffu, part3, 1);
    float4 r4 = make_float4(0.f, 0.f, 0.f, 0.f);
    bool valid = (seg == 0) && (gm < Nn);
    float lmax = -3.4e38f;
    if(valid){
        r4 = make_float4(part0 + bp2[0], part1 + bp2[1], part2 + bp2[2], part3 + bp2[3]);
        *(float4*)(g_pl + gm*4) = r4;
        lmax = fmaxf(fmaxf(r4.x, r4.y), fmaxf(r4.z, r4.w));
    }
    float* red = (float*)As;
    red[t] = lmax; __syncthreads();
    for(int o = 64; o > 0; o >>= 1){ if(t < o) red[t] = fmaxf(red[t], red[t+o]); __syncthreads(); }
    float M = red[0]; __syncthreads();
    float ls = 0.f;
    if(valid)
        ls = __expf(r4.x - M) + __expf(r4.y - M) + __expf(r4.z - M) + __expf(r4.w - M);
    red[t] = ls; __syncthreads();
    for(int o = 64; o > 0; o >>= 1){ if(t < o) red[t] += red[t+o]; __syncthreads(); }
    if(t == 0){ g_pmax[blockIdx.x] = M; g_psum[blockIdx.x] = red[0]; }
}

// ---------------- output: combine partials + softmax + restore replay state ------
__global__ void k_out(float* __restrict__ out){
    __shared__ float sm[256];
    __shared__ float sMS[2];
    int tid = threadIdx.x;
    float m = (tid < NRED) ? g_pmax[tid] : -3.4e38f;
    sm[tid] = m; __syncthreads();
    for(int o = 128; o > 0; o >>= 1){ if(tid < o) sm[tid] = fmaxf(sm[tid], sm[tid+o]); __syncthreads(); }
    float M = sm[0]; __syncthreads();
    float s = (tid < NRED) ? g_psum[tid] * __expf(g_pmax[tid] - M) : 0.f;
    sm[tid] = s; __syncthreads();
    for(int o = 128; o > 0; o >>= 1){ if(tid < o) sm[tid] += sm[tid+o]; __syncthreads(); }
    if(tid == 0){ sMS[0] = M; sMS[1] = 1.f / sm[0]; }
    __syncthreads();
    int i = blockIdx.x*blockDim.x + tid;
    if(i < Nn*4) out[i] = __expf(g_pl[i] - sMS[0]) * sMS[1];
    if(i < Nn) g_cl[i] = make_float2(0.f, 0.f);
}

// ---------------- launch ----------------
extern "C" void kernel_launch(void* const* d_in, const int* in_sizes, int n_in,
                              void* d_out, int out_size){
    const float* x     = (const float*)d_in[0];
    const int*   ei    = (const int*)  d_in[1];
    const float* ea    = (const float*)d_in[2];
    const float* Wl1   = (const float*)d_in[3];
    const float* bl1   = (const float*)d_in[4];
    const float* Wr1   = (const float*)d_in[5];
    const float* br1   = (const float*)d_in[6];
    const float* We1   = (const float*)d_in[7];
    const float* att1  = (const float*)d_in[8];
    const float* bias1 = (const float*)d_in[9];
    const float* g1    = (const float*)d_in[10];
    const float* be1   = (const float*)d_in[11];
    const float* Wl2   = (const float*)d_in[12];
    const float* bl2   = (const float*)d_in[13];
    const float* Wr2   = (const float*)d_in[14];
    const float* br2   = (const float*)d_in[15];
    const float* We2   = (const float*)d_in[16];
    const float* att2  = (const float*)d_in[17];
    const float* bias2 = (const float*)d_in[18];
    const float* g2    = (const float*)d_in[19];
    const float* be2   = (const float*)d_in[20];
    const float* Wp1   = (const float*)d_in[21];
    const float* bp1   = (const float*)d_in[22];
    const float* Wp2   = (const float*)d_in[23];
    const float* bp2   = (const float*)d_in[24];
    const int* src = ei;
    const int* dst = ei + Ne;
    float* out = (float*)d_out;

    const int TB = 256;

    // CSR build + conv1 linear (merged)
    k_hist_lin1<<<HB + (Nn*64+TB-1)/TB, TB>>>(dst, ea, x, Wl1, bl1, Wr1, br1);
    k_scanprep<<<1, 1024>>>(x);
    k_scatter<<<(Ne+TB-1)/TB, TB>>>(src, dst, ea, x);

    // conv1 (low-rank aggregation, half2 logits, packed-x edge records)
    k_conv1lr<<<Nn, 32>>>(Wl1, bl1, We1, att1, bias1, g1, be1);

    // conv2 (fp16 tensor-core dual GEMM)
    k_gemm_dual<<<dim3(8, (Nn+63)/64), 128>>>(Wl2, bl2, Wr2, br2);
    k_conv2<<<Nn, 32>>>(We2, att2, bias2, g2, be2);

    // policy head (fp16 TC GEMM + fused projection + softmax partials)
    k_gemm_pol<<<NRED, 128>>>(Wp1, bp1, Wp2, bp2);

    // output
    k_out<<<(Nn*4+TB-1)/TB, TB>>>(out);
}

// round 17
// speedup vs baseline: 1.0551x; 1.0551x over previous
#include <cuda_runtime.h>
#include <cuda_fp16.h>
#include <mma.h>
using namespace nvcuda;

#define Nn   10000
#define Ne   320000
#define EAt  330000      // edges + self loops
#define HID  256
#define NRED 157         // one partial per gemm_pol block

// ---------------- scratch (static device globals; zero-initialized at load) ------
__device__ float2   g_cl[Nn];          // (incoming count, edge_attr sum)
__device__ int      g_row[Nn+1];
__device__ int      g_woff[Nn];
__device__ int2     g_ced[EAt];        // (src, ea_bits)
__device__ __half2  g_xlh[Nn*128];     // fp16 xl feature table (edge-gathered)
__device__ __half2  g_hh[Nn*128];      // fp16 activations: conv1 out, then conv2 out
__device__ float    g_xr[Nn*HID];
__device__ float    g_pl[Nn*4];
__device__ float    g_pmax[NRED];
__device__ float    g_psum[NRED];

__device__ __forceinline__ void red2(float2* p, float a, float b){
    asm volatile("red.global.add.v2.f32 [%0], {%1,%2};" :: "l"(p), "f"(a), "f"(b) : "memory");
}

// half2 logit kernel -> per-lane partial as __half
__device__ __forceinline__ __half dot8hh(const __half2* la, const __half2* rh,
                                         const __half2* wh, const __half2* a06,
                                         const __half2* a04, __half2 evh){
    __half2 pa = __float2half2_rn(0.f), pb = __float2half2_rn(0.f);
    #pragma unroll
    for(int j4 = 0; j4 < 4; j4++){
        __half2 z = __hfma2(evh, wh[j4], __hadd2(la[j4], rh[j4]));
        pa = __hfma2(z, a06[j4], pa);
        pb = __hfma2(__habs2(z), a04[j4], pb);
    }
    __half2 s = __hadd2(pa, pb);
    return __hadd(__low2half(s), __high2half(s));
}

// packed butterfly reduce of two logits over 2^NSH lanes
template<int NSH>
__device__ __forceinline__ float2 red2h(__half2 ph){
    unsigned u = *(unsigned*)&ph;
    #pragma unroll
    for(int o = 0; o < NSH; o++){
        unsigned v = __shfl_xor_sync(0xffffffffu, u, 1 << o);
        __half2 a = *(__half2*)&u, b = *(__half2*)&v;
        __half2 r = __hadd2(a, b);
        u = *(unsigned*)&r;
    }
    return __half22float2(*(__half2*)&u);
}

// ---------------- kernel 1: edge histogram (vector red)  ||  lin1 ----------------
#define HB 1250   // (Ne+255)/256
__global__ void k_hist_lin1(const int* __restrict__ dst, const float* __restrict__ ea,
                            const float* __restrict__ x,
                            const float* __restrict__ Wl, const float* __restrict__ bl,
                            const float* __restrict__ Wr, const float* __restrict__ br){
    int b = blockIdx.x;
    if(b < HB){
        int e = b*256 + threadIdx.x;
        if(e < Ne)
            red2(&g_cl[dst[e]], 1.f, ea[e]);
    } else {
        int t = (b - HB)*256 + threadIdx.x;
        if(t < Nn*64){
            int n = t >> 6, c4 = (t & 63) << 2;
            float4 xv = *(const float4*)(x + n*4);
            float4 l = *(const float4*)(bl + c4);
            float4 r = *(const float4*)(br + c4);
            float4 w;
            w = *(const float4*)(Wl + 0*256 + c4); l.x+=xv.x*w.x; l.y+=xv.x*w.y; l.z+=xv.x*w.z; l.w+=xv.x*w.w;
            w = *(const float4*)(Wl + 1*256 + c4); l.x+=xv.y*w.x; l.y+=xv.y*w.y; l.z+=xv.y*w.z; l.w+=xv.y*w.w;
            w = *(const float4*)(Wl + 2*256 + c4); l.x+=xv.z*w.x; l.y+=xv.z*w.y; l.z+=xv.z*w.z; l.w+=xv.z*w.w;
            w = *(const float4*)(Wl + 3*256 + c4); l.x+=xv.w*w.x; l.y+=xv.w*w.y; l.z+=xv.w*w.z; l.w+=xv.w*w.w;
            w = *(const float4*)(Wr + 0*256 + c4); r.x+=xv.x*w.x; r.y+=xv.x*w.y; r.z+=xv.x*w.z; r.w+=xv.x*w.w;
            w = *(const float4*)(Wr + 1*256 + c4); r.x+=xv.y*w.x; r.y+=xv.y*w.y; r.z+=xv.y*w.z; r.w+=xv.y*w.w;
            w = *(const float4*)(Wr + 2*256 + c4); r.x+=xv.z*w.x; r.y+=xv.z*w.y; r.z+=xv.z*w.z; r.w+=xv.z*w.w;
            w = *(const float4*)(Wr + 3*256 + c4); r.x+=xv.w*w.x; r.y+=xv.w*w.y; r.z+=xv.w*w.z; r.w+=xv.w*w.w;
            __half2 h0 = __floats2half2_rn(l.x, l.y);
            __half2 h1 = __floats2half2_rn(l.z, l.w);
            __half2* dst2 = g_xlh + n*128 + (c4 >> 1);
            dst2[0] = h0; dst2[1] = h1;
            *(float4*)(g_xr + n*256 + c4) = r;
        }
    }
}

// ---------------- kernel 2: scan + prep (single block) ----------------
__global__ void k_scanprep(){
    __shared__ int part[1024];
    const int NP = 10;
    int tid = threadIdx.x;
    int base = tid * NP;
    int cnt[NP], loc[NP];
    int s = 0;
    #pragma unroll
    for(int i = 0; i < NP; i++){
        int idx = base + i;
        int c = (idx < Nn) ? (int)g_cl[idx].x : 0;
        cnt[i] = c;
        loc[i] = s;
        s += (idx < Nn) ? (c + 1) : 0;
    }
    part[tid] = s; __syncthreads();
    for(int o = 1; o < 1024; o <<= 1){
        int v = (tid >= o) ? part[tid - o] : 0;
        __syncthreads();
        if(tid >= o) part[tid] += v;
        __syncthreads();
    }
    int off = (tid > 0) ? part[tid - 1] : 0;
    #pragma unroll
    for(int i = 0; i < NP; i++){
        int idx = base + i;
        if(idx < Nn){
            int rs = off + loc[i];
            int re = rs + cnt[i] + 1;
            g_row[idx] = rs;
            if(idx == Nn-1) g_row[Nn] = re;
            float lp = g_cl[idx].y / fmaxf((float)cnt[i], 1.f);
            g_ced[re-1] = make_int2(idx, __float_as_int(lp));
            g_woff[idx] = rs;
        }
    }
}

// ---------------- kernel 3: scatter edges into CSR ----------------
__global__ void k_scatter(const int* __restrict__ src, const int* __restrict__ dst,
                          const float* __restrict__ ea){
    int e = blockIdx.x*blockDim.x + threadIdx.x;
    if(e >= Ne) return;
    int d = dst[e];
    int pos = atomicAdd(&g_woff[d], 1);
    g_ced[pos] = make_int2(src[e], __float_as_int(ea[e]));
}

// ---------------- fused conv1 (low-rank aggregation; packed half2 reduction) -----
__global__ void __launch_bounds__(32) k_conv1lr(
        const float* __restrict__ x,
        const float* __restrict__ Wl, const float* __restrict__ bl,
        const float* __restrict__ We, const float* __restrict__ att,
        const float* __restrict__ bias, const float* __restrict__ gam,
        const float* __restrict__ bet){
    int n = blockIdx.x;
    int lane = threadIdx.x;
    int c0 = lane * 8;
    __half2 rh[4], wh[4], a06[4], a04[4];
    {
        float4 rA = *(const float4*)(g_xr + n*HID + c0);
        float4 rB = *(const float4*)(g_xr + n*HID + c0 + 4);
        rh[0] = __floats2half2_rn(rA.x, rA.y); rh[1] = __floats2half2_rn(rA.z, rA.w);
        rh[2] = __floats2half2_rn(rB.x, rB.y); rh[3] = __floats2half2_rn(rB.z, rB.w);
        float4 wA = *(const float4*)(We + c0), wB = *(const float4*)(We + c0 + 4);
        wh[0] = __floats2half2_rn(wA.x, wA.y); wh[1] = __floats2half2_rn(wA.z, wA.w);
        wh[2] = __floats2half2_rn(wB.x, wB.y); wh[3] = __floats2half2_rn(wB.z, wB.w);
        float4 tA = *(const float4*)(att + c0), tB = *(const float4*)(att + c0 + 4);
        a06[0] = __floats2half2_rn(0.6f*tA.x, 0.6f*tA.y); a06[1] = __floats2half2_rn(0.6f*tA.z, 0.6f*tA.w);
        a06[2] = __floats2half2_rn(0.6f*tB.x, 0.6f*tB.y); a06[3] = __floats2half2_rn(0.6f*tB.z, 0.6f*tB.w);
        a04[0] = __floats2half2_rn(0.4f*tA.x, 0.4f*tA.y); a04[1] = __floats2half2_rn(0.4f*tA.z, 0.4f*tA.w);
        a04[2] = __floats2half2_rn(0.4f*tB.x, 0.4f*tB.y); a04[3] = __floats2half2_rn(0.4f*tB.z, 0.4f*tB.w);
    }
    int j = lane & 3;
    float acc1 = 0.f, den = 0.f;
    int b = g_row[n], e = g_row[n+1];
    int i = b;
    for(; i + 1 < e; i += 2){
        int2 ed0 = g_ced[i], ed1 = g_ced[i+1];
        uint4 raw0 = *(const uint4*)(g_xlh + ed0.x*128 + lane*4);
        uint4 raw1 = *(const uint4*)(g_xlh + ed1.x*128 + lane*4);
        const __half2* la = (const __half2*)&raw0;
        const __half2* lb = (const __half2*)&raw1;
        __half2 evh0 = __float2half2_rn(__int_as_float(ed0.y));
        __half2 evh1 = __float2half2_rn(__int_as_float(ed1.y));
        float xs0 = x[ed0.x*4 + j];
        float xs1 = x[ed1.x*4 + j];
        __half h0 = dot8hh(la, rh, wh, a06, a04, evh0);
        __half h1 = dot8hh(lb, rh, wh, a06, a04, evh1);
        float2 pf = red2h<3>(__halves2half2(h0, h1));
        float e0 = __expf(pf.x);
        float e1 = __expf(pf.y);
        den += e0 + e1;
        acc1 += xs0*e0 + xs1*e1;
    }
    if(i < e){
        int2 ed0 = g_ced[i];
        uint4 raw0 = *(const uint4*)(g_xlh + ed0.x*128 + lane*4);
        const __half2* la = (const __half2*)&raw0;
        __half2 evh0 = __float2half2_rn(__int_as_float(ed0.y));
        float xs0 = x[ed0.x*4 + j];
        __half h0 = dot8hh(la, rh, wh, a06, a04, evh0);
        float2 pf = red2h<3>(__halves2half2(h0, __float2half_rn(0.f)));
        float e0 = __expf(pf.x);
        den += e0;
        acc1 += xs0*e0;
    }
    float inv = 1.f / den;
    int h8 = lane & 24;
    float ax0 = __shfl_sync(0xffffffffu, acc1, h8+0) * inv;
    float ax1 = __shfl_sync(0xffffffffu, acc1, h8+1) * inv;
    float ax2 = __shfl_sync(0xffffffffu, acc1, h8+2) * inv;
    float ax3 = __shfl_sync(0xffffffffu, acc1, h8+3) * inv;
    float4 wr0A = *(const float4*)(Wl + 0*256 + c0), wr0B = *(const float4*)(Wl + 0*256 + c0 + 4);
    float4 wr1A = *(const float4*)(Wl + 1*256 + c0), wr1B = *(const float4*)(Wl + 1*256 + c0 + 4);
    float4 wr2A = *(const float4*)(Wl + 2*256 + c0), wr2B = *(const float4*)(Wl + 2*256 + c0 + 4);
    float4 wr3A = *(const float4*)(Wl + 3*256 + c0), wr3B = *(const float4*)(Wl + 3*256 + c0 + 4);
    float4 blA = *(const float4*)(bl + c0),   blB = *(const float4*)(bl + c0 + 4);
    float4 biA = *(const float4*)(bias + c0), biB = *(const float4*)(bias + c0 + 4);
    float v[8];
    v[0] = ax0*wr0A.x + ax1*wr1A.x + ax2*wr2A.x + ax3*wr3A.x + blA.x + biA.x;
    v[1] = ax0*wr0A.y + ax1*wr1A.y + ax2*wr2A.y + ax3*wr3A.y + blA.y + biA.y;
    v[2] = ax0*wr0A.z + ax1*wr1A.z + ax2*wr2A.z + ax3*wr3A.z + blA.z + biA.z;
    v[3] = ax0*wr0A.w + ax1*wr1A.w + ax2*wr2A.w + ax3*wr3A.w + blA.w + biA.w;
    v[4] = ax0*wr0B.x + ax1*wr1B.x + ax2*wr2B.x + ax3*wr3B.x + blB.x + biB.x;
    v[5] = ax0*wr0B.y + ax1*wr1B.y + ax2*wr2B.y + ax3*wr3B.y + blB.y + biB.y;
    v[6] = ax0*wr0B.z + ax1*wr1B.z + ax2*wr2B.z + ax3*wr3B.z + blB.z + biB.z;
    v[7] = ax0*wr0B.w + ax1*wr1B.w + ax2*wr2B.w + ax3*wr3B.w + blB.w + biB.w;
    float s = 0.f;
    #pragma unroll
    for(int k = 0; k < 8; k++) s += v[k];
    #pragma unroll
    for(int o = 16; o; o >>= 1) s += __shfl_xor_sync(0xffffffffu, s, o);
    float mu = s * (1.f/256.f);
    float q = 0.f;
    #pragma unroll
    for(int k = 0; k < 8; k++){ float dd = v[k]-mu; q += dd*dd; }
    #pragma unroll
    for(int o = 16; o; o >>= 1) q += __shfl_xor_sync(0xffffffffu, q, o);
    float rstd = rsqrtf(q*(1.f/256.f) + 1e-5f);
    float4 gA = *(const float4*)(gam + c0), gB = *(const float4*)(gam + c0 + 4);
    float4 eA = *(const float4*)(bet + c0), eB = *(const float4*)(bet + c0 + 4);
    float gv[8] = {gA.x,gA.y,gA.z,gA.w,gB.x,gB.y,gB.z,gB.w};
    float ev[8] = {eA.x,eA.y,eA.z,eA.w,eB.x,eB.y,eB.z,eB.w};
    float o0[8];
    #pragma unroll
    for(int k = 0; k < 8; k++)
        o0[k] = fmaxf((v[k]-mu)*rstd*gv[k] + ev[k], 0.f);
    __half2* dh = g_hh + n*128 + lane*4;
    dh[0] = __floats2half2_rn(o0[0], o0[1]);
    dh[1] = __floats2half2_rn(o0[2], o0[3]);
    dh[2] = __floats2half2_rn(o0[4], o0[5]);
    dh[3] = __floats2half2_rn(o0[6], o0[7]);
}

// ---------------- fused conv2: packed half2 reduction + half2 agg w/ flush -------
__global__ void __launch_bounds__(32) k_conv2(
        const float* __restrict__ We, const float* __restrict__ att,
        const float* __restrict__ bias, const float* __restrict__ gam,
        const float* __restrict__ bet){
    int n = blockIdx.x;
    int lane = threadIdx.x;
    int c0 = lane * 8;
    __half2 rh[4], wh[4], a06[4], a04[4];
    {
        float4 rA = *(const float4*)(g_xr + n*HID + c0);
        float4 rB = *(const float4*)(g_xr + n*HID + c0 + 4);
        rh[0] = __floats2half2_rn(rA.x, rA.y); rh[1] = __floats2half2_rn(rA.z, rA.w);
        rh[2] = __floats2half2_rn(rB.x, rB.y); rh[3] = __floats2half2_rn(rB.z, rB.w);
        float4 wA = *(const float4*)(We + c0), wB = *(const float4*)(We + c0 + 4);
        wh[0] = __floats2half2_rn(wA.x, wA.y); wh[1] = __floats2half2_rn(wA.z, wA.w);
        wh[2] = __floats2half2_rn(wB.x, wB.y); wh[3] = __floats2half2_rn(wB.z, wB.w);
        float4 tA = *(const float4*)(att + c0), tB = *(const float4*)(att + c0 + 4);
        a06[0] = __floats2half2_rn(0.6f*tA.x, 0.6f*tA.y); a06[1] = __floats2half2_rn(0.6f*tA.z, 0.6f*tA.w);
        a06[2] = __floats2half2_rn(0.6f*tB.x, 0.6f*tB.y); a06[3] = __floats2half2_rn(0.6f*tB.z, 0.6f*tB.w);
        a04[0] = __floats2half2_rn(0.4f*tA.x, 0.4f*tA.y); a04[1] = __floats2half2_rn(0.4f*tA.z, 0.4f*tA.w);
        a04[2] = __floats2half2_rn(0.4f*tB.x, 0.4f*tB.y); a04[3] = __floats2half2_rn(0.4f*tB.z, 0.4f*tB.w);
    }
    float acc[8] = {0,0,0,0,0,0,0,0};
    __half2 zero2 = __float2half2_rn(0.f);
    __half2 hacc[4] = {zero2, zero2, zero2, zero2};
    float den = 0.f;
    int flush = 0;
    int b = g_row[n], e = g_row[n+1];
    int i = b;
    for(; i + 1 < e; i += 2){
        int2 ed0 = g_ced[i], ed1 = g_ced[i+1];
        uint4 raw0 = *(const uint4*)(g_xlh + ed0.x*128 + lane*4);
        uint4 raw1 = *(const uint4*)(g_xlh + ed1.x*128 + lane*4);
        const __half2* la = (const __half2*)&raw0;
        const __half2* lb = (const __half2*)&raw1;
        __half2 evh0 = __float2half2_rn(__int_as_float(ed0.y));
        __half2 evh1 = __float2half2_rn(__int_as_float(ed1.y));
        __half h0 = dot8hh(la, rh, wh, a06, a04, evh0);
        __half h1 = dot8hh(lb, rh, wh, a06, a04, evh1);
        float2 pf = red2h<5>(__halves2half2(h0, h1));
        float e0 = __expf(pf.x);
        float e1 = __expf(pf.y);
        den += e0 + e1;
        __half2 eh0 = __float2half2_rn(e0);
        __half2 eh1 = __float2half2_rn(e1);
        #pragma unroll
        for(int j4 = 0; j4 < 4; j4++){
            hacc[j4] = __hfma2(la[j4], eh0, hacc[j4]);
            hacc[j4] = __hfma2(lb[j4], eh1, hacc[j4]);
        }
        if(++flush == 4){
            flush = 0;
            #pragma unroll
            for(int j4 = 0; j4 < 4; j4++){
                float2 f = __half22float2(hacc[j4]);
                acc[2*j4]   += f.x;
                acc[2*j4+1] += f.y;
                hacc[j4] = zero2;
            }
        }
    }
    if(i < e){
        int2 ed0 = g_ced[i];
        uint4 raw0 = *(const uint4*)(g_xlh + ed0.x*128 + lane*4);
        const __half2* la = (const __half2*)&raw0;
        __half2 evh0 = __float2half2_rn(__int_as_float(ed0.y));
        __half h0 = dot8hh(la, rh, wh, a06, a04, evh0);
        float2 pf = red2h<5>(__halves2half2(h0, __float2half_rn(0.f)));
        float e0 = __expf(pf.x);
        den += e0;
        __half2 eh0 = __float2half2_rn(e0);
        #pragma unroll
        for(int j4 = 0; j4 < 4; j4++)
            hacc[j4] = __hfma2(la[j4], eh0, hacc[j4]);
    }
    #pragma unroll
    for(int j4 = 0; j4 < 4; j4++){
        float2 f = __half22float2(hacc[j4]);
        acc[2*j4]   += f.x;
        acc[2*j4+1] += f.y;
    }
    float inv = 1.f / den;
    float4 biA = *(const float4*)(bias + c0), biB = *(const float4*)(bias + c0 + 4);
    float bi[8] = {biA.x,biA.y,biA.z,biA.w,biB.x,biB.y,biB.z,biB.w};
    float v[8];
    float s = 0.f;
    #pragma unroll
    for(int k = 0; k < 8; k++){ v[k] = acc[k]*inv + bi[k]; s += v[k]; }
    #pragma unroll
    for(int o = 16; o; o >>= 1) s += __shfl_xor_sync(0xffffffffu, s, o);
    float mu = s * (1.f/256.f);
    float q = 0.f;
    #pragma unroll
    for(int k = 0; k < 8; k++){ float dd = v[k]-mu; q += dd*dd; }
    #pragma unroll
    for(int o = 16; o; o >>= 1) q += __shfl_xor_sync(0xffffffffu, q, o);
    float rstd = rsqrtf(q*(1.f/256.f) + 1e-5f);
    float4 gA = *(const float4*)(gam + c0), gB = *(const float4*)(gam + c0 + 4);
    float4 eA = *(const float4*)(bet + c0), eB = *(const float4*)(bet + c0 + 4);
    float gv[8] = {gA.x,gA.y,gA.z,gA.w,gB.x,gB.y,gB.z,gB.w};
    float evv[8] = {eA.x,eA.y,eA.z,eA.w,eB.x,eB.y,eB.z,eB.w};
    float o0[8];
    #pragma unroll
    for(int k = 0; k < 8; k++)
        o0[k] = fmaxf((v[k]-mu)*rstd*gv[k] + evv[k], 0.f);
    __half2* dh = g_hh + n*128 + lane*4;
    dh[0] = __floats2half2_rn(o0[0], o0[1]);
    dh[1] = __floats2half2_rn(o0[2], o0[3]);
    dh[2] = __floats2half2_rn(o0[4], o0[5]);
    dh[3] = __floats2half2_rn(o0[6], o0[7]);
}

// ---------------- dual GEMM: fp16 tensor cores (m16n16k16, fp32 accum) ----------
__global__ void __launch_bounds__(128) k_gemm_dual(
        const float* __restrict__ Wl, const float* __restrict__ bl,
        const float* __restrict__ Wr, const float* __restrict__ br){
    __shared__ __align__(16) __half As[64][40];
    __shared__ __align__(16) __half Bs[32][72];
    __shared__ __align__(16) float  Cs[64][68];
    int half_ = blockIdx.x >> 2;
    int nblk = blockIdx.x & 3;
    const float* B    = half_ ? Wr : Wl;
    const float* bias = half_ ? br : bl;
    int m0 = blockIdx.y*64, n0 = nblk*64;
    int t = threadIdx.x;
    int warp = t >> 5, wy = warp >> 1, wx = warp & 1;

    wmma::fragment<wmma::accumulator,16,16,16,float> acc[2][2];
    #pragma unroll
    for(int i = 0; i < 2; i++)
        #pragma unroll
        for(int jj = 0; jj < 2; jj++)
            wmma::fill_fragment(acc[i][jj], 0.f);

    int arow = t >> 1, aseg = t & 1;
    int brow = t >> 2, bcol = (t & 3) * 16;
    for(int k0 = 0; k0 < 256; k0 += 32){
        int gm = m0 + arow;
        uint4 z4 = make_uint4(0,0,0,0);
        const uint4* srcA = (const uint4*)(g_hh + gm*128 + (k0 >> 1) + aseg*8);
        uint4 av0 = (gm < Nn) ? srcA[0] : z4;
        uint4 av1 = (gm < Nn) ? srcA[1] : z4;
        *(uint4*)&As[arow][aseg*16]     = av0;
        *(uint4*)&As[arow][aseg*16 + 8] = av1;
        const float4* srcB = (const float4*)(B + (k0+brow)*256 + n0 + bcol);
        float4 f0 = srcB[0], f1 = srcB[1], f2 = srcB[2], f3 = srcB[3];
        __half2* db = (__half2*)&Bs[brow][bcol];
        db[0] = __floats2half2_rn(f0.x,f0.y); db[1] = __floats2half2_rn(f0.z,f0.w);
        db[2] = __floats2half2_rn(f1.x,f1.y); db[3] = __floats2half2_rn(f1.z,f1.w);
        db[4] = __floats2half2_rn(f2.x,f2.y); db[5] = __floats2half2_rn(f2.z,f2.w);
        db[6] = __floats2half2_rn(f3.x,f3.y); db[7] = __floats2half2_rn(f3.z,f3.w);
        __syncthreads();
        #pragma unroll
        for(int ks = 0; ks < 2; ks++){
            wmma::fragment<wmma::matrix_a,16,16,16,__half,wmma::row_major> af[2];
            wmma::fragment<wmma::matrix_b,16,16,16,__half,wmma::row_major> bf[2];
            #pragma unroll
            for(int i = 0; i < 2; i++)
                wmma::load_matrix_sync(af[i], &As[wy*32 + i*16][ks*16], 40);
            #pragma unroll
            for(int jj = 0; jj < 2; jj++)
                wmma::load_matrix_sync(bf[jj], &Bs[ks*16][wx*32 + jj*16], 72);
            #pragma unroll
            for(int i = 0; i < 2; i++)
                #pragma unroll
                for(int jj = 0; jj < 2; jj++)
                    wmma::mma_sync(acc[i][jj], af[i], bf[jj], acc[i][jj]);
        }
        __syncthreads();
    }
    #pragma unroll
    for(int i = 0; i < 2; i++)
        #pragma unroll
        for(int jj = 0; jj < 2; jj++)
            wmma::store_matrix_sync(&Cs[wy*32 + i*16][wx*32 + jj*16], acc[i][jj], 68, wmma::mem_row_major);
    __syncthreads();
    for(int idx = t; idx < 64*16; idx += 128){
        int row = idx >> 4;
        int c4 = (idx & 15) * 4;
        int gm = m0 + row;
        if(gm >= Nn) continue;
        float4 v = *(float4*)&Cs[row][c4];
        float4 bv = *(const float4*)(bias + n0 + c4);
        v.x += bv.x; v.y += bv.y; v.z += bv.z; v.w += bv.w;
        if(half_){
            *(float4*)(g_xr + gm*256 + n0 + c4) = v;
        } else {
            __half2* d2 = g_xlh + gm*128 + ((n0 + c4) >> 1);
            d2[0] = __floats2half2_rn(v.x, v.y);
            d2[1] = __floats2half2_rn(v.z, v.w);
        }
    }
}

// ---------------- policy GEMM: fp16 TC + fused Wp2 projection + softmax partials --
__global__ void __launch_bounds__(128) k_gemm_pol(
        const float* __restrict__ Wp1, const float* __restrict__ bp1,
        const float* __restrict__ Wp2, const float* __restrict__ bp2){
    __shared__ __align__(16) __half As[64][40];
    __shared__ __align__(16) __half Bs[32][136];
    __shared__ __align__(16) float  Cs[64][132];
    int m0 = blockIdx.x * 64;
    int t = threadIdx.x;
    int warp = t >> 5, wy = warp >> 1, wx = warp & 1;

    wmma::fragment<wmma::accumulator,16,16,16,float> acc[2][4];
    #pragma unroll
    for(int i = 0; i < 2; i++)
        #pragma unroll
        for(int jj = 0; jj < 4; jj++)
            wmma::fill_fragment(acc[i][jj], 0.f);

    int arow = t >> 1, aseg = t & 1;
    int brow = t >> 2, bcol = (t & 3) * 32;
    for(int k0 = 0; k0 < 256; k0 += 32){
        int gm = m0 + arow;
        uint4 z4 = make_uint4(0,0,0,0);
        const uint4* srcA = (const uint4*)(g_hh + gm*128 + (k0 >> 1) + aseg*8);
        uint4 av0 = (gm < Nn) ? srcA[0] : z4;
        uint4 av1 = (gm < Nn) ? srcA[1] : z4;
        *(uint4*)&As[arow][aseg*16]     = av0;
        *(uint4*)&As[arow][aseg*16 + 8] = av1;
        const float4* srcB = (const float4*)(Wp1 + (k0+brow)*128 + bcol);
        __half2* db = (__half2*)&Bs[brow][bcol];
        #pragma unroll
        for(int q = 0; q < 8; q++){
            float4 f = srcB[q];
            db[2*q]   = __floats2half2_rn(f.x, f.y);
            db[2*q+1] = __floats2half2_rn(f.z, f.w);
        }
        __syncthreads();
        #pragma unroll
        for(int ks = 0; ks < 2; ks++){
            wmma::fragment<wmma::matrix_a,16,16,16,__half,wmma::row_major> af[2];
            wmma::fragment<wmma::matrix_b,16,16,16,__half,wmma::row_major> bf[4];
            #pragma unroll
            for(int i = 0; i < 2; i++)
                wmma::load_matrix_sync(af[i], &As[wy*32 + i*16][ks*16], 40);
            #pragma unroll
            for(int jj = 0; jj < 4; jj++)
                wmma::load_matrix_sync(bf[jj], &Bs[ks*16][wx*64 + jj*16], 136);
            #pragma unroll
            for(int i = 0; i < 2; i++)
                #pragma unroll
                for(int jj = 0; jj < 4; jj++)
                    wmma::mma_sync(acc[i][jj], af[i], bf[jj], acc[i][jj]);
        }
        __syncthreads();
    }
    #pragma unroll
    for(int i = 0; i < 2; i++)
        #pragma unroll
        for(int jj = 0; jj < 4; jj++)
            wmma::store_matrix_sync(&Cs[wy*32 + i*16][wx*64 + jj*16], acc[i][jj], 132, wmma::mem_row_major);
    __syncthreads();
    int row = t >> 1;
    int seg = t & 1;
    int gm = m0 + row;
    float part0 = 0.f, part1 = 0.f, part2 = 0.f, part3 = 0.f;
    #pragma unroll 8
    for(int jq = 0; jq < 64; jq++){
        int col = seg*64 + jq;
        float v = fmaxf(Cs[row][col] + bp1[col], 0.f);
        const float4 wv = *(const float4*)(Wp2 + col*4);
        part0 += v*wv.x; part1 += v*wv.y; part2 += v*wv.z; part3 += v*wv.w;
    }
    part0 += __shfl_xor_sync(0xffffffffu, part0, 1);
    part1 += __shfl_xor_sync(0xffffffffu, part1, 1);
    part2 += __shfl_xor_sync(0xffffffffu, part2, 1);
    part3 += __shfl_xor_sync(0xffffffffu, part3, 1);
    float4 r4 = make_float4(0.f, 0.f, 0.f, 0.f);
    bool valid = (seg == 0) && (gm < Nn);
    float lmax = -3.4e38f;
    if(valid){
        r4 = make_float4(part0 + bp2[0], part1 + bp2[1], part2 + bp2[2], part3 + bp2[3]);
        *(float4*)(g_pl + gm*4) = r4;
        lmax = fmaxf(fmaxf(r4.x, r4.y), fmaxf(r4.z, r4.w));
    }
    float* red = (float*)As;
    red[t] = lmax; __syncthreads();
    for(int o = 64; o > 0; o >>= 1){ if(t < o) red[t] = fmaxf(red[t], red[t+o]); __syncthreads(); }
    float M = red[0]; __syncthreads();
    float ls = 0.f;
    if(valid)
        ls = __expf(r4.x - M) + __expf(r4.y - M) + __expf(r4.z - M) + __expf(r4.w - M);
    red[t] = ls; __syncthreads();
    for(int o = 64; o > 0; o >>= 1){ if(t < o) red[t] += red[t+o]; __syncthreads(); }
    if(t == 0){ g_pmax[blockIdx.x] = M; g_psum[blockIdx.x] = red[0]; }
}

// ---------------- output: combine partials + softmax + restore replay state ------
__global__ void k_out(float* __restrict__ out){
    __shared__ float sm[256];
    __shared__ float sMS[2];
    int tid = threadIdx.x;
    float m = (tid < NRED) ? g_pmax[tid] : -3.4e38f;
    sm[tid] = m; __syncthreads();
    for(int o = 128; o > 0; o >>= 1){ if(tid < o) sm[tid] = fmaxf(sm[tid], sm[tid+o]); __syncthreads(); }
    float M = sm[0]; __syncthreads();
    float s = (tid < NRED) ? g_psum[tid] * __expf(g_pmax[tid] - M) : 0.f;
    sm[tid] = s; __syncthreads();
    for(int o = 128; o > 0; o >>= 1){ if(tid < o) sm[tid] += sm[tid+o]; __syncthreads(); }
    if(tid == 0){ sMS[0] = M; sMS[1] = 1.f / sm[0]; }
    __syncthreads();
    int i = blockIdx.x*blockDim.x + tid;
    if(i < Nn*4) out[i] = __expf(g_pl[i] - sMS[0]) * sMS[1];
    if(i < Nn) g_cl[i] = make_float2(0.f, 0.f);
}

// ---------------- launch ----------------
extern "C" void kernel_launch(void* const* d_in, const int* in_sizes, int n_in,
                              void* d_out, int out_size){
    const float* x     = (const float*)d_in[0];
    const int*   ei    = (const int*)  d_in[1];
    const float* ea    = (const float*)d_in[2];
    const float* Wl1   = (const float*)d_in[3];
    const float* bl1   = (const float*)d_in[4];
    const float* Wr1   = (const float*)d_in[5];
    const float* br1   = (const float*)d_in[6];
    const float* We1   = (const float*)d_in[7];
    const float* att1  = (const float*)d_in[8];
    const float* bias1 = (const float*)d_in[9];
    const float* g1    = (const float*)d_in[10];
    const float* be1   = (const float*)d_in[11];
    const float* Wl2   = (const float*)d_in[12];
    const float* bl2   = (const float*)d_in[13];
    const float* Wr2   = (const float*)d_in[14];
    const float* br2   = (const float*)d_in[15];
    const float* We2   = (const float*)d_in[16];
    const float* att2  = (const float*)d_in[17];
    const float* bias2 = (const float*)d_in[18];
    const float* g2    = (const float*)d_in[19];
    const float* be2   = (const float*)d_in[20];
    const float* Wp1   = (const float*)d_in[21];
    const float* bp1   = (const float*)d_in[22];
    const float* Wp2   = (const float*)d_in[23];
    const float* bp2   = (const float*)d_in[24];
    const int* src = ei;
    const int* dst = ei + Ne;
    float* out = (float*)d_out;

    const int TB = 256;

    // CSR build + conv1 linear (merged)
    k_hist_lin1<<<HB + (Nn*64+TB-1)/TB, TB>>>(dst, ea, x, Wl1, bl1, Wr1, br1);
    k_scanprep<<<1, 1024>>>();
    k_scatter<<<(Ne+TB-1)/TB, TB>>>(src, dst, ea);

    // conv1 (low-rank aggregation, packed half2 reduction)
    k_conv1lr<<<Nn, 32>>>(x, Wl1, bl1, We1, att1, bias1, g1, be1);

    // conv2 (fp16 tensor-core dual GEMM)
    k_gemm_dual<<<dim3(8, (Nn+63)/64), 128>>>(Wl2, bl2, Wr2, br2);
    k_conv2<<<Nn, 32>>>(We2, att2, bias2, g2, be2);

    // policy head (fp16 TC GEMM + fused projection + softmax partials)
    k_gemm_pol<<<NRED, 128>>>(Wp1, bp1, Wp2, bp2);

    // output
    k_out<<<(Nn*4+TB-1)/TB, TB>>>(out);
}